// round 3
// baseline (speedup 1.0000x reference)
#include <cuda_runtime.h>
#include <math.h>
#include <stdint.h>

// Problem constants (fixed by the reference)
#define DMODEL 1024
#define NEXP   8
#define TOPK   2
#define DFF    4096
#define NTOK   4096          // B*S = 2*2048
#define EPS_LN 1e-5f
#define EPS_TK 1e-8f

// ---------------------------------------------------------------------------
// Scratch (device globals: no allocations allowed)
// ---------------------------------------------------------------------------
__device__ float g_xn[(size_t)NTOK * DMODEL];                 // 16 MB  normalized input
__device__ float g_h [(size_t)NTOK * TOPK * DFF];             // 134 MB GEMM1 output (post-gelu)
__device__ float g_y [(size_t)NTOK * TOPK * DMODEL];          // 33 MB  GEMM2 output (weighted)
__device__ int   g_cnt [NEXP];
__device__ int   g_fill[NEXP];
__device__ int   g_off [NEXP + 1];
__device__ int   g_tok [NTOK * TOPK];                         // token id per assignment row
__device__ float g_wt  [NTOK * TOPK];                         // combine weight per assignment row
__device__ int   g_slot[NTOK * TOPK];                         // per token: its 2 assignment rows
__device__ int   g_te  [NTOK * TOPK];                         // per token: chosen experts
__device__ float g_tw  [NTOK * TOPK];                         // per token: weights

// ---------------------------------------------------------------------------
// Small helpers
// ---------------------------------------------------------------------------
__device__ __forceinline__ uint32_t f2tf32(float x) {
    uint32_t u;
    asm("cvt.rna.tf32.f32 %0, %1;" : "=r"(u) : "f"(x));
    return u;
}

__device__ __forceinline__ void mma_tf32(float* c, const uint32_t* a, const uint32_t* b) {
    asm volatile(
        "mma.sync.aligned.m16n8k8.row.col.f32.tf32.tf32.f32 "
        "{%0,%1,%2,%3}, {%4,%5,%6,%7}, {%8,%9}, {%0,%1,%2,%3};\n"
        : "+f"(c[0]), "+f"(c[1]), "+f"(c[2]), "+f"(c[3])
        : "r"(a[0]), "r"(a[1]), "r"(a[2]), "r"(a[3]), "r"(b[0]), "r"(b[1]));
}

__device__ __forceinline__ void cp_async16(uint32_t smem_addr, const void* gptr, unsigned src_bytes) {
    asm volatile("cp.async.cg.shared.global [%0], [%1], 16, %2;\n"
                 :: "r"(smem_addr), "l"(gptr), "r"(src_bytes));
}

__device__ __forceinline__ float gelu_exact(float v) {
    return 0.5f * v * (1.0f + erff(v * 0.70710678118654752f));
}

// ---------------------------------------------------------------------------
// Kernel 0: zero counters
// ---------------------------------------------------------------------------
__global__ void zero_kernel() {
    int i = threadIdx.x;
    if (i < NEXP) { g_cnt[i] = 0; g_fill[i] = 0; }
}

// ---------------------------------------------------------------------------
// Kernel 1: fused LayerNorm + router (softmax + top-2) per token
// one block (256 threads) per token
// ---------------------------------------------------------------------------
__global__ void ln_router_kernel(const float* __restrict__ x,
                                 const float* __restrict__ gamma,
                                 const float* __restrict__ beta,
                                 const float* __restrict__ Wg,
                                 const float* __restrict__ bg) {
    __shared__ float xsh[DMODEL];
    __shared__ float s_sum[8], s_sq[8];
    __shared__ float s_stats[2];
    __shared__ float s_log[NEXP];

    const int t    = blockIdx.x;
    const int tid  = threadIdx.x;
    const int lane = tid & 31;
    const int wid  = tid >> 5;

    const float4 v = reinterpret_cast<const float4*>(x + (size_t)t * DMODEL)[tid];
    float ssum = v.x + v.y + v.z + v.w;
    float ssq  = v.x * v.x + v.y * v.y + v.z * v.z + v.w * v.w;
    #pragma unroll
    for (int o = 16; o; o >>= 1) {
        ssum += __shfl_xor_sync(0xFFFFFFFFu, ssum, o);
        ssq  += __shfl_xor_sync(0xFFFFFFFFu, ssq, o);
    }
    if (lane == 0) { s_sum[wid] = ssum; s_sq[wid] = ssq; }
    __syncthreads();
    if (tid == 0) {
        float a = 0.f, b = 0.f;
        #pragma unroll
        for (int i = 0; i < 8; i++) { a += s_sum[i]; b += s_sq[i]; }
        float mu  = a / (float)DMODEL;
        float var = b / (float)DMODEL - mu * mu;
        s_stats[0] = mu;
        s_stats[1] = rsqrtf(var + EPS_LN);
    }
    __syncthreads();
    const float mu = s_stats[0], rstd = s_stats[1];

    const float4 g  = reinterpret_cast<const float4*>(gamma)[tid];
    const float4 bb = reinterpret_cast<const float4*>(beta)[tid];
    float4 o;
    o.x = (v.x - mu) * rstd * g.x + bb.x;
    o.y = (v.y - mu) * rstd * g.y + bb.y;
    o.z = (v.z - mu) * rstd * g.z + bb.z;
    o.w = (v.w - mu) * rstd * g.w + bb.w;
    reinterpret_cast<float4*>(g_xn + (size_t)t * DMODEL)[tid] = o;
    reinterpret_cast<float4*>(xsh)[tid] = o;
    __syncthreads();

    // warp e computes logit e: dot(xn, Wg[e]) + bg[e]
    {
        const float* wrow = Wg + wid * DMODEL;
        float acc = 0.f;
        for (int i = lane; i < DMODEL; i += 32) acc += xsh[i] * wrow[i];
        #pragma unroll
        for (int oo = 16; oo; oo >>= 1) acc += __shfl_xor_sync(0xFFFFFFFFu, acc, oo);
        if (lane == 0) s_log[wid] = acc + bg[wid];
    }
    __syncthreads();

    if (tid == 0) {
        float m = -1e30f;
        #pragma unroll
        for (int i = 0; i < NEXP; i++) m = fmaxf(m, s_log[i]);
        float p[NEXP]; float Z = 0.f;
        #pragma unroll
        for (int i = 0; i < NEXP; i++) { p[i] = expf(s_log[i] - m); Z += p[i]; }
        #pragma unroll
        for (int i = 0; i < NEXP; i++) p[i] /= Z;
        // top-2, first-occurrence tie-break (matches jax top_k)
        int i0 = 0; float p0 = p[0];
        #pragma unroll
        for (int i = 1; i < NEXP; i++) if (p[i] > p0) { p0 = p[i]; i0 = i; }
        int i1 = -1; float p1 = -1e30f;
        #pragma unroll
        for (int i = 0; i < NEXP; i++) if (i != i0 && p[i] > p1) { p1 = p[i]; i1 = i; }
        float denom = p0 + p1 + EPS_TK;
        g_te[2 * t]     = i0;  g_tw[2 * t]     = p0 / denom;
        g_te[2 * t + 1] = i1;  g_tw[2 * t + 1] = p1 / denom;
        atomicAdd(&g_cnt[i0], 1);
        atomicAdd(&g_cnt[i1], 1);
    }
}

// ---------------------------------------------------------------------------
// Kernel 2: exclusive prefix over 8 expert counts
// ---------------------------------------------------------------------------
__global__ void offsets_kernel() {
    if (threadIdx.x == 0) {
        int o = 0;
        #pragma unroll
        for (int e = 0; e < NEXP; e++) { g_off[e] = o; o += g_cnt[e]; }
        g_off[NEXP] = o;
    }
}

// ---------------------------------------------------------------------------
// Kernel 3: scatter tokens into contiguous per-expert assignment lists
// ---------------------------------------------------------------------------
__global__ void scatter_kernel() {
    int t = blockIdx.x * blockDim.x + threadIdx.x;
    if (t >= NTOK) return;
    #pragma unroll
    for (int k = 0; k < TOPK; k++) {
        int e   = g_te[2 * t + k];
        int pos = atomicAdd(&g_fill[e], 1);
        int r   = g_off[e] + pos;
        g_tok[r] = t;
        g_wt[r]  = g_tw[2 * t + k];
        g_slot[2 * t + k] = r;
    }
}

// ---------------------------------------------------------------------------
// Kernels 4/5: tf32 tensor-core grouped GEMM.
//   GELU=true  : h = gelu(Xn[gather] @ W1[e]^T + b1[e])        (N=DFF, K=DMODEL)
//   GELU=false : y = (H @ W2[e]^T + b2[e]) * combine_weight    (N=DMODEL, K=DFF)
// Block tile 128x128, BK=16, cp.async double-buffered, 8 warps of 32x64.
// ---------------------------------------------------------------------------
template <int NTOT, int KDIM, bool GELU>
__global__ __launch_bounds__(256, 2)
void moe_gemm_kernel(const float* __restrict__ Wbase,
                     const float* __restrict__ bias) {
    constexpr int BM = 128, BN = 128, BK = 16, LDS = BK + 4;
    __shared__ float As[2][BM][LDS];
    __shared__ float Bs[2][BN][LDS];

    const float* Abase = GELU ? g_xn : g_h;
    float*       Out   = GELU ? g_h  : g_y;

    const int e   = blockIdx.z;
    const int cnt = g_cnt[e];
    const int m0  = blockIdx.y * BM;
    if (m0 >= cnt) return;
    const int off = g_off[e];
    const int n0  = blockIdx.x * BN;

    const int tid  = threadIdx.x;
    const int lane = tid & 31;
    const int wid  = tid >> 5;
    const int wm   = (wid >> 1) * 32;   // warp grid 4x2, warp tile 32x64
    const int wn   = (wid & 1) * 64;
    const int grp  = lane >> 2;         // 0..7
    const int tig  = lane & 3;          // 0..3

    // per-thread loader state: 2 float4s of A and 2 float4s of B per tile
    const float* aptr[2]; unsigned abytes[2]; uint32_t offA[2];
    const float* bptr[2];
    #pragma unroll
    for (int i = 0; i < 2; i++) {
        int f4  = tid + i * 256;
        int row = f4 >> 2;
        int q   = f4 & 3;
        int gm  = m0 + row;
        bool v  = gm < cnt;
        long arow;
        if (GELU) arow = v ? (long)g_tok[off + gm] : 0L;   // gather token rows of xn
        else      arow = v ? (long)(off + gm)      : 0L;   // contiguous rows of h
        aptr[i]   = Abase + (size_t)arow * KDIM + q * 4;
        abytes[i] = v ? 16u : 0u;
        offA[i]   = (uint32_t)((row * LDS + q * 4) * 4);
        bptr[i]   = Wbase + ((size_t)e * NTOT + n0 + row) * (size_t)KDIM + q * 4;
    }
    const uint32_t asb = (uint32_t)__cvta_generic_to_shared(&As[0][0][0]);
    const uint32_t bsb = (uint32_t)__cvta_generic_to_shared(&Bs[0][0][0]);
    constexpr uint32_t BUFB = BM * LDS * 4;

    float acc[2][8][4];
    #pragma unroll
    for (int a = 0; a < 2; a++)
        #pragma unroll
        for (int b = 0; b < 8; b++)
            #pragma unroll
            for (int c = 0; c < 4; c++) acc[a][b][c] = 0.f;

    auto load_tile = [&](int kt, int buf) {
        #pragma unroll
        for (int i = 0; i < 2; i++) {
            cp_async16(asb + buf * BUFB + offA[i], aptr[i] + kt * BK, abytes[i]);
            cp_async16(bsb + buf * BUFB + offA[i], bptr[i] + kt * BK, 16u);
        }
    };

    load_tile(0, 0);
    asm volatile("cp.async.commit_group;\n" ::);

    const int KT = KDIM / BK;
    for (int kt = 0; kt < KT; ++kt) {
        if (kt + 1 < KT) {
            load_tile(kt + 1, (kt + 1) & 1);
            asm volatile("cp.async.commit_group;\n" ::);
            asm volatile("cp.async.wait_group 1;\n" ::);
        } else {
            asm volatile("cp.async.wait_group 0;\n" ::);
        }
        __syncthreads();

        const int b = kt & 1;
        #pragma unroll
        for (int k8 = 0; k8 < BK / 8; k8++) {
            const int kb = k8 * 8;
            uint32_t au[2][4];
            #pragma unroll
            for (int im = 0; im < 2; im++) {
                int r = wm + im * 16 + grp;
                au[im][0] = f2tf32(As[b][r][kb + tig]);
                au[im][1] = f2tf32(As[b][r + 8][kb + tig]);
                au[im][2] = f2tf32(As[b][r][kb + tig + 4]);
                au[im][3] = f2tf32(As[b][r + 8][kb + tig + 4]);
            }
            uint32_t bu[8][2];
            #pragma unroll
            for (int jn = 0; jn < 8; jn++) {
                int c = wn + jn * 8 + grp;
                bu[jn][0] = f2tf32(Bs[b][c][kb + tig]);
                bu[jn][1] = f2tf32(Bs[b][c][kb + tig + 4]);
            }
            #pragma unroll
            for (int im = 0; im < 2; im++)
                #pragma unroll
                for (int jn = 0; jn < 8; jn++)
                    mma_tf32(acc[im][jn], au[im], bu[jn]);
        }
        __syncthreads();
    }

    // epilogue
    #pragma unroll
    for (int im = 0; im < 2; im++) {
        #pragma unroll
        for (int half = 0; half < 2; half++) {
            int rl = wm + im * 16 + grp + half * 8;
            int gm = m0 + rl;
            if (gm >= cnt) continue;
            int grow = off + gm;
            float scale = 1.0f;
            if (!GELU) scale = g_wt[grow];
            float* orow = Out + (size_t)grow * NTOT;
            const float* brow = bias + (size_t)e * NTOT;
            #pragma unroll
            for (int jn = 0; jn < 8; jn++) {
                int col = n0 + wn + jn * 8 + tig * 2;
                float c0 = acc[im][jn][half * 2 + 0] + brow[col];
                float c1 = acc[im][jn][half * 2 + 1] + brow[col + 1];
                if (GELU) { c0 = gelu_exact(c0); c1 = gelu_exact(c1); }
                else      { c0 *= scale;        c1 *= scale; }
                float2 st; st.x = c0; st.y = c1;
                *reinterpret_cast<float2*>(orow + col) = st;
            }
        }
    }
}

// ---------------------------------------------------------------------------
// Kernel 6: residual combine  out[t] = x[t] + y[slot0] + y[slot1]
// ---------------------------------------------------------------------------
__global__ void combine_kernel(const float* __restrict__ x, float* __restrict__ out) {
    const int t   = blockIdx.x;
    const int tid = threadIdx.x;
    const int s0  = g_slot[2 * t];
    const int s1  = g_slot[2 * t + 1];
    const float4 xv = reinterpret_cast<const float4*>(x + (size_t)t * DMODEL)[tid];
    const float4 y0 = reinterpret_cast<const float4*>(g_y + (size_t)s0 * DMODEL)[tid];
    const float4 y1 = reinterpret_cast<const float4*>(g_y + (size_t)s1 * DMODEL)[tid];
    float4 o;
    o.x = xv.x + y0.x + y1.x;
    o.y = xv.y + y0.y + y1.y;
    o.z = xv.z + y0.z + y1.z;
    o.w = xv.w + y0.w + y1.w;
    reinterpret_cast<float4*>(out + (size_t)t * DMODEL)[tid] = o;
}

// ---------------------------------------------------------------------------
// Entry point
// ---------------------------------------------------------------------------
extern "C" void kernel_launch(void* const* d_in, const int* in_sizes, int n_in,
                              void* d_out, int out_size) {
    (void)in_sizes; (void)n_in; (void)out_size;
    const float* x     = (const float*)d_in[0];
    const float* gamma = (const float*)d_in[1];
    const float* beta  = (const float*)d_in[2];
    const float* Wg    = (const float*)d_in[3];
    const float* bg    = (const float*)d_in[4];
    const float* W1    = (const float*)d_in[5];
    const float* b1    = (const float*)d_in[6];
    const float* W2    = (const float*)d_in[7];
    const float* b2    = (const float*)d_in[8];
    float* out = (float*)d_out;

    zero_kernel<<<1, 32>>>();
    ln_router_kernel<<<NTOK, 256>>>(x, gamma, beta, Wg, bg);
    offsets_kernel<<<1, 1>>>();
    scatter_kernel<<<(NTOK + 255) / 256, 256>>>();
    // GEMM1: h = gelu(xn @ W1^T + b1), per expert; worst case M = NTOK
    moe_gemm_kernel<DFF, DMODEL, true>
        <<<dim3(DFF / 128, NTOK / 128, NEXP), 256>>>(W1, b1);
    // GEMM2: y = (h @ W2^T + b2) * w, per expert
    moe_gemm_kernel<DMODEL, DFF, false>
        <<<dim3(DMODEL / 128, NTOK / 128, NEXP), 256>>>(W2, b2);
    combine_kernel<<<NTOK, 256>>>(x, out);
}

// round 6
// speedup vs baseline: 1.6601x; 1.6601x over previous
#include <cuda_runtime.h>
#include <cuda_fp16.h>
#include <math.h>
#include <stdint.h>

// Problem constants (fixed by the reference)
#define DMODEL 1024
#define NEXP   8
#define TOPK   2
#define DFF    4096
#define NTOK   4096          // B*S = 2*2048
#define EPS_LN 1e-5f
#define EPS_TK 1e-8f

// ---------------------------------------------------------------------------
// Scratch (device globals: no allocations allowed)
// ---------------------------------------------------------------------------
__device__ __half g_xnh[(size_t)NTOK * DMODEL];                // 8 MB   normalized input (fp16)
__device__ __half g_hh [(size_t)NTOK * TOPK * DFF];            // 67 MB  GEMM1 output (post-gelu, fp16)
__device__ float  g_y  [(size_t)NTOK * TOPK * DMODEL];         // 33 MB  GEMM2 output (weighted)
__device__ __half g_w1h[(size_t)NEXP * DFF * DMODEL];          // 67 MB  W1 fp16
__device__ __half g_w2h[(size_t)NEXP * DMODEL * DFF];          // 67 MB  W2 fp16
__device__ int    g_cnt [NEXP];
__device__ int    g_fill[NEXP];
__device__ int    g_off [NEXP + 1];
__device__ int    g_tok [NTOK * TOPK];
__device__ float  g_wt  [NTOK * TOPK];
__device__ int    g_slot[NTOK * TOPK];
__device__ int    g_te  [NTOK * TOPK];
__device__ float  g_tw  [NTOK * TOPK];

// ---------------------------------------------------------------------------
// Helpers
// ---------------------------------------------------------------------------
__device__ __forceinline__ uint32_t smem_u32(const void* p) {
    uint32_t a;
    asm("{ .reg .u64 t; cvta.to.shared.u64 t, %1; cvt.u32.u64 %0, t; }" : "=r"(a) : "l"(p));
    return a;
}

__device__ __forceinline__ void cp_async16(uint32_t saddr, const void* g, unsigned src_bytes) {
    asm volatile("cp.async.cg.shared.global [%0], [%1], 16, %2;\n"
                 :: "r"(saddr), "l"(g), "r"(src_bytes));
}

__device__ __forceinline__ void ldsm_x4(uint32_t& r0, uint32_t& r1, uint32_t& r2, uint32_t& r3,
                                        uint32_t addr) {
    asm volatile("ldmatrix.sync.aligned.m8n8.x4.shared.b16 {%0,%1,%2,%3}, [%4];"
                 : "=r"(r0), "=r"(r1), "=r"(r2), "=r"(r3) : "r"(addr));
}

__device__ __forceinline__ void mma_f16(float* c, const uint32_t* a, const uint32_t* b) {
    asm volatile("mma.sync.aligned.m16n8k16.row.col.f32.f16.f16.f32 "
                 "{%0,%1,%2,%3}, {%4,%5,%6,%7}, {%8,%9}, {%0,%1,%2,%3};"
                 : "+f"(c[0]), "+f"(c[1]), "+f"(c[2]), "+f"(c[3])
                 : "r"(a[0]), "r"(a[1]), "r"(a[2]), "r"(a[3]), "r"(b[0]), "r"(b[1]));
}

__device__ __forceinline__ float gelu_exact(float v) {
    return 0.5f * v * (1.0f + erff(v * 0.70710678118654752f));
}

// ---------------------------------------------------------------------------
// Kernel 0: zero counters
// ---------------------------------------------------------------------------
__global__ void zero_kernel() {
    int i = threadIdx.x;
    if (i < NEXP) { g_cnt[i] = 0; g_fill[i] = 0; }
}

// ---------------------------------------------------------------------------
// Kernel W: f32 -> fp16 weight conversion (elementwise)
// ---------------------------------------------------------------------------
__global__ void cvt_kernel(const float* __restrict__ src, __half* __restrict__ dst) {
    const int i = blockIdx.x * blockDim.x + threadIdx.x;   // one float4 per thread
    const float4 v = reinterpret_cast<const float4*>(src)[i];
    __half2 h0 = __floats2half2_rn(v.x, v.y);
    __half2 h1 = __floats2half2_rn(v.z, v.w);
    reinterpret_cast<__half2*>(dst)[2 * i]     = h0;
    reinterpret_cast<__half2*>(dst)[2 * i + 1] = h1;
}

// ---------------------------------------------------------------------------
// Kernel 1: fused LayerNorm + router (softmax + top-2) per token.
// Router uses full f32 xn (top-2 picks can't flip); g_xnh stored fp16 for GEMM.
// ---------------------------------------------------------------------------
__global__ void ln_router_kernel(const float* __restrict__ x,
                                 const float* __restrict__ gamma,
                                 const float* __restrict__ beta,
                                 const float* __restrict__ Wg,
                                 const float* __restrict__ bg) {
    __shared__ float xsh[DMODEL];
    __shared__ float s_sum[8], s_sq[8];
    __shared__ float s_stats[2];
    __shared__ float s_log[NEXP];

    const int t    = blockIdx.x;
    const int tid  = threadIdx.x;
    const int lane = tid & 31;
    const int wid  = tid >> 5;

    const float4 v = reinterpret_cast<const float4*>(x + (size_t)t * DMODEL)[tid];
    float ssum = v.x + v.y + v.z + v.w;
    float ssq  = v.x * v.x + v.y * v.y + v.z * v.z + v.w * v.w;
    #pragma unroll
    for (int o = 16; o; o >>= 1) {
        ssum += __shfl_xor_sync(0xFFFFFFFFu, ssum, o);
        ssq  += __shfl_xor_sync(0xFFFFFFFFu, ssq, o);
    }
    if (lane == 0) { s_sum[wid] = ssum; s_sq[wid] = ssq; }
    __syncthreads();
    if (tid == 0) {
        float a = 0.f, b = 0.f;
        #pragma unroll
        for (int i = 0; i < 8; i++) { a += s_sum[i]; b += s_sq[i]; }
        float mu  = a / (float)DMODEL;
        float var = b / (float)DMODEL - mu * mu;
        s_stats[0] = mu;
        s_stats[1] = rsqrtf(var + EPS_LN);
    }
    __syncthreads();
    const float mu = s_stats[0], rstd = s_stats[1];

    const float4 g  = reinterpret_cast<const float4*>(gamma)[tid];
    const float4 bb = reinterpret_cast<const float4*>(beta)[tid];
    float4 o;
    o.x = (v.x - mu) * rstd * g.x + bb.x;
    o.y = (v.y - mu) * rstd * g.y + bb.y;
    o.z = (v.z - mu) * rstd * g.z + bb.z;
    o.w = (v.w - mu) * rstd * g.w + bb.w;
    reinterpret_cast<float4*>(xsh)[tid] = o;   // full precision for router
    __half2 h0 = __floats2half2_rn(o.x, o.y);
    __half2 h1 = __floats2half2_rn(o.z, o.w);
    __half2* xr = reinterpret_cast<__half2*>(g_xnh + (size_t)t * DMODEL);
    xr[2 * tid]     = h0;
    xr[2 * tid + 1] = h1;
    __syncthreads();

    // warp e computes logit e
    {
        const float* wrow = Wg + wid * DMODEL;
        float acc = 0.f;
        for (int i = lane; i < DMODEL; i += 32) acc += xsh[i] * wrow[i];
        #pragma unroll
        for (int oo = 16; oo; oo >>= 1) acc += __shfl_xor_sync(0xFFFFFFFFu, acc, oo);
        if (lane == 0) s_log[wid] = acc + bg[wid];
    }
    __syncthreads();

    if (tid == 0) {
        float m = -1e30f;
        #pragma unroll
        for (int i = 0; i < NEXP; i++) m = fmaxf(m, s_log[i]);
        float p[NEXP]; float Z = 0.f;
        #pragma unroll
        for (int i = 0; i < NEXP; i++) { p[i] = expf(s_log[i] - m); Z += p[i]; }
        #pragma unroll
        for (int i = 0; i < NEXP; i++) p[i] /= Z;
        int i0 = 0; float p0 = p[0];
        #pragma unroll
        for (int i = 1; i < NEXP; i++) if (p[i] > p0) { p0 = p[i]; i0 = i; }
        int i1 = -1; float p1 = -1e30f;
        #pragma unroll
        for (int i = 0; i < NEXP; i++) if (i != i0 && p[i] > p1) { p1 = p[i]; i1 = i; }
        float denom = p0 + p1 + EPS_TK;
        g_te[2 * t]     = i0;  g_tw[2 * t]     = p0 / denom;
        g_te[2 * t + 1] = i1;  g_tw[2 * t + 1] = p1 / denom;
        atomicAdd(&g_cnt[i0], 1);
        atomicAdd(&g_cnt[i1], 1);
    }
}

// ---------------------------------------------------------------------------
// Kernel 2/3: offsets + scatter
// ---------------------------------------------------------------------------
__global__ void offsets_kernel() {
    if (threadIdx.x == 0) {
        int o = 0;
        #pragma unroll
        for (int e = 0; e < NEXP; e++) { g_off[e] = o; o += g_cnt[e]; }
        g_off[NEXP] = o;
    }
}

__global__ void scatter_kernel() {
    int t = blockIdx.x * blockDim.x + threadIdx.x;
    if (t >= NTOK) return;
    #pragma unroll
    for (int k = 0; k < TOPK; k++) {
        int e   = g_te[2 * t + k];
        int pos = atomicAdd(&g_fill[e], 1);
        int r   = g_off[e] + pos;
        g_tok[r] = t;
        g_wt[r]  = g_tw[2 * t + k];
        g_slot[2 * t + k] = r;
    }
}

// ---------------------------------------------------------------------------
// Kernels 4/5: fp16 mma.sync grouped GEMM (ldmatrix + cp.async, 4 stages).
//   GELU=true  : h = gelu(Xn[gather] @ W1[e]^T + b1[e])   (N=DFF, K=DMODEL)
//   GELU=false : y = (H @ W2[e]^T + b2[e]) * w            (N=DMODEL, K=DFF)
// CTA 128x128, BK=64 halves (128B rows, SW128 swizzle). 8 warps of 64x32.
// ---------------------------------------------------------------------------
#define BM 128
#define BN 128
#define BK 64
#define ATILE (BM * BK * 2)               // 16384 B
#define BTILE (BN * BK * 2)               // 16384 B
#define STAGE (ATILE + BTILE)             // 32768 B
#define NSTAGE 4
#define GEMM_SMEM (NSTAGE * STAGE)        // 131072 B

template <int NTOT, int KDIM, bool GELU>
__global__ __launch_bounds__(256)
void moe_hgemm(const __half* __restrict__ Wh, const float* __restrict__ bias) {
    constexpr int KT = KDIM / BK;

    const int e   = blockIdx.z;
    const int cnt = g_cnt[e];
    const int m0  = blockIdx.y * BM;
    if (m0 >= cnt) return;
    const int off = g_off[e];
    const int n0  = blockIdx.x * BN;

    extern __shared__ char smem[];
    const uint32_t sb = smem_u32(smem);
    const int tid  = threadIdx.x;
    const int lane = tid & 31;
    const int wid  = tid >> 5;
    const int wm   = (wid & 1) * 64;      // warp grid 2(M) x 4(N)
    const int wn   = (wid >> 1) * 32;
    const int grp  = lane >> 2;
    const int tig  = lane & 3;

    // --- loader precompute: 4 A + 4 B chunks of 16B per thread per stage ---
    const __half* Asrc = GELU ? g_xnh : g_hh;
    const __half* aptr[4]; unsigned abyt[4]; uint32_t aoff[4];
    const __half* bptr[4]; uint32_t boff[4];
    #pragma unroll
    for (int i = 0; i < 4; i++) {
        int lin = tid + i * 256;           // 0..1023
        int row = lin >> 3, q = lin & 7;
        int gm  = m0 + row;
        bool v  = gm < cnt;
        long ar = GELU ? (v ? (long)g_tok[off + gm] : 0L)
                       : (v ? (long)(off + gm)      : 0L);
        aptr[i] = Asrc + (size_t)ar * KDIM + q * 8;
        abyt[i] = v ? 16u : 0u;
        aoff[i] = (uint32_t)(row * 128 + ((q ^ (row & 7)) * 16));
        bptr[i] = Wh + ((size_t)e * NTOT + n0 + row) * (size_t)KDIM + q * 8;
        boff[i] = aoff[i] + ATILE;
    }

    auto load_stage = [&](int kt) {
        const uint32_t base = sb + (kt & (NSTAGE - 1)) * STAGE;
        #pragma unroll
        for (int i = 0; i < 4; i++) cp_async16(base + aoff[i], aptr[i] + kt * BK, abyt[i]);
        #pragma unroll
        for (int i = 0; i < 4; i++) cp_async16(base + boff[i], bptr[i] + kt * BK, 16u);
        asm volatile("cp.async.commit_group;\n" ::);
    };

    // per-lane ldmatrix row constants (8 rows per tile; lane>>3 selects subtile)
    const int lrow = (lane & 7) + ((lane >> 3) & 1) * 8;   // row within 16-row frag
    const int hi   = lane >> 4;                             // k-granule subtile (0/1)

    float acc[4][4][4];
    #pragma unroll
    for (int a = 0; a < 4; a++)
        #pragma unroll
        for (int b = 0; b < 4; b++)
            #pragma unroll
            for (int c = 0; c < 4; c++) acc[a][b][c] = 0.f;

    load_stage(0); load_stage(1); load_stage(2);

    for (int kt = 0; kt < KT; ++kt) {
        if (kt < KT - 2)      asm volatile("cp.async.wait_group 2;\n" ::);
        else if (kt == KT - 2) asm volatile("cp.async.wait_group 1;\n" ::);
        else                   asm volatile("cp.async.wait_group 0;\n" ::);
        __syncthreads();

        if (kt + 3 < KT) load_stage(kt + 3);

        const uint32_t base = sb + (kt & (NSTAGE - 1)) * STAGE;
        #pragma unroll
        for (int ks = 0; ks < 4; ks++) {
            const int gk = ks * 2 + hi;   // k-granule index for this lane's subtile
            uint32_t a[4][4], bf[4][2];
            #pragma unroll
            for (int mf = 0; mf < 4; mf++) {
                int r = wm + mf * 16 + lrow;
                uint32_t addr = base + r * 128 + ((gk ^ (r & 7)) * 16);
                ldsm_x4(a[mf][0], a[mf][1], a[mf][2], a[mf][3], addr);
            }
            #pragma unroll
            for (int nf2 = 0; nf2 < 2; nf2++) {
                int r = wn + nf2 * 16 + lrow;
                uint32_t addr = base + ATILE + r * 128 + ((gk ^ (r & 7)) * 16);
                uint32_t r0, r1, r2, r3;
                ldsm_x4(r0, r1, r2, r3, addr);
                bf[nf2 * 2 + 0][0] = r0; bf[nf2 * 2 + 0][1] = r2;
                bf[nf2 * 2 + 1][0] = r1; bf[nf2 * 2 + 1][1] = r3;
            }
            #pragma unroll
            for (int mf = 0; mf < 4; mf++)
                #pragma unroll
                for (int nf = 0; nf < 4; nf++)
                    mma_f16(acc[mf][nf], a[mf], bf[nf]);
        }
    }

    // --- epilogue ---
    const float* brow = bias + (size_t)e * NTOT;
    #pragma unroll
    for (int mf = 0; mf < 4; mf++) {
        #pragma unroll
        for (int half = 0; half < 2; half++) {
            const int rl = wm + mf * 16 + grp + half * 8;
            const int gm = m0 + rl;
            if (gm >= cnt) continue;
            const int grow = off + gm;
            if (GELU) {
                __half* orow = g_hh + (size_t)grow * NTOT;
                #pragma unroll
                for (int nf = 0; nf < 4; nf++) {
                    const int col = n0 + wn + nf * 8 + tig * 2;
                    float c0 = acc[mf][nf][half * 2 + 0] + brow[col];
                    float c1 = acc[mf][nf][half * 2 + 1] + brow[col + 1];
                    *reinterpret_cast<__half2*>(orow + col) =
                        __floats2half2_rn(gelu_exact(c0), gelu_exact(c1));
                }
            } else {
                const float scale = g_wt[grow];
                float* orow = g_y + (size_t)grow * NTOT;
                #pragma unroll
                for (int nf = 0; nf < 4; nf++) {
                    const int col = n0 + wn + nf * 8 + tig * 2;
                    float2 st;
                    st.x = (acc[mf][nf][half * 2 + 0] + brow[col])     * scale;
                    st.y = (acc[mf][nf][half * 2 + 1] + brow[col + 1]) * scale;
                    *reinterpret_cast<float2*>(orow + col) = st;
                }
            }
        }
    }
}

// ---------------------------------------------------------------------------
// Kernel 6: residual combine  out[t] = x[t] + y[slot0] + y[slot1]
// ---------------------------------------------------------------------------
__global__ void combine_kernel(const float* __restrict__ x, float* __restrict__ out) {
    const int t   = blockIdx.x;
    const int tid = threadIdx.x;
    const int s0  = g_slot[2 * t];
    const int s1  = g_slot[2 * t + 1];
    const float4 xv = reinterpret_cast<const float4*>(x + (size_t)t * DMODEL)[tid];
    const float4 y0 = reinterpret_cast<const float4*>(g_y + (size_t)s0 * DMODEL)[tid];
    const float4 y1 = reinterpret_cast<const float4*>(g_y + (size_t)s1 * DMODEL)[tid];
    float4 o;
    o.x = xv.x + y0.x + y1.x;
    o.y = xv.y + y0.y + y1.y;
    o.z = xv.z + y0.z + y1.z;
    o.w = xv.w + y0.w + y1.w;
    reinterpret_cast<float4*>(out + (size_t)t * DMODEL)[tid] = o;
}

// ---------------------------------------------------------------------------
// Entry point
// ---------------------------------------------------------------------------
extern "C" void kernel_launch(void* const* d_in, const int* in_sizes, int n_in,
                              void* d_out, int out_size) {
    (void)in_sizes; (void)n_in; (void)out_size;
    const float* x     = (const float*)d_in[0];
    const float* gamma = (const float*)d_in[1];
    const float* beta  = (const float*)d_in[2];
    const float* Wg    = (const float*)d_in[3];
    const float* bg    = (const float*)d_in[4];
    const float* W1    = (const float*)d_in[5];
    const float* b1    = (const float*)d_in[6];
    const float* W2    = (const float*)d_in[7];
    const float* b2    = (const float*)d_in[8];
    float* out = (float*)d_out;

    cudaFuncSetAttribute(moe_hgemm<DFF, DMODEL, true>,
                         cudaFuncAttributeMaxDynamicSharedMemorySize, GEMM_SMEM);
    cudaFuncSetAttribute(moe_hgemm<DMODEL, DFF, false>,
                         cudaFuncAttributeMaxDynamicSharedMemorySize, GEMM_SMEM);

    __half* w1h; cudaGetSymbolAddress((void**)&w1h, g_w1h);
    __half* w2h; cudaGetSymbolAddress((void**)&w2h, g_w2h);

    const int WELEM = NEXP * DFF * DMODEL;          // 33,554,432
    cvt_kernel<<<WELEM / (256 * 4), 256>>>(W1, w1h);
    cvt_kernel<<<WELEM / (256 * 4), 256>>>(W2, w2h);

    zero_kernel<<<1, 32>>>();
    ln_router_kernel<<<NTOK, 256>>>(x, gamma, beta, Wg, bg);
    offsets_kernel<<<1, 1>>>();
    scatter_kernel<<<(NTOK + 255) / 256, 256>>>();

    // GEMM1: h = gelu(xn @ W1^T + b1)
    moe_hgemm<DFF, DMODEL, true>
        <<<dim3(DFF / BN, NTOK / BM, NEXP), 256, GEMM_SMEM>>>(w1h, b1);
    // GEMM2: y = (h @ W2^T + b2) * w
    moe_hgemm<DMODEL, DFF, false>
        <<<dim3(DMODEL / BN, NTOK / BM, NEXP), 256, GEMM_SMEM>>>(w2h, b2);

    combine_kernel<<<NTOK, 256>>>(x, out);
}

// round 9
// speedup vs baseline: 1.8425x; 1.1099x over previous
#include <cuda_runtime.h>
#include <cuda_fp16.h>
#include <math.h>
#include <stdint.h>

// Problem constants (fixed by the reference)
#define DMODEL 1024
#define NEXP   8
#define TOPK   2
#define NTOK   4096          // B*S = 2*2048
#define DFF    4096
#define EPS_LN 1e-5f
#define EPS_TK 1e-8f

// ---------------------------------------------------------------------------
// Scratch (device globals: no allocations allowed)
// ---------------------------------------------------------------------------
__device__ __half g_xnh[(size_t)NTOK * DMODEL];                // 8 MB   normalized input (fp16)
__device__ __half g_hh [(size_t)NTOK * TOPK * DFF];            // 67 MB  GEMM1 output (post-gelu, fp16)
__device__ float  g_y  [(size_t)NTOK * TOPK * DMODEL];         // 33 MB  GEMM2 output (weighted)
__device__ __half g_w1h[(size_t)NEXP * DFF * DMODEL];          // 67 MB  W1 fp16
__device__ __half g_w2h[(size_t)NEXP * DMODEL * DFF];          // 67 MB  W2 fp16
__device__ int    g_cnt [NEXP];
__device__ int    g_fill[NEXP];
__device__ int    g_off [NEXP + 1];
__device__ int    g_tok [NTOK * TOPK];
__device__ float  g_wt  [NTOK * TOPK];
__device__ int    g_slot[NTOK * TOPK];
__device__ int    g_te  [NTOK * TOPK];
__device__ float  g_tw  [NTOK * TOPK];

// ---------------------------------------------------------------------------
// Helpers
// ---------------------------------------------------------------------------
__device__ __forceinline__ uint32_t smem_u32(const void* p) {
    uint32_t a;
    asm("{ .reg .u64 t; cvta.to.shared.u64 t, %1; cvt.u32.u64 %0, t; }" : "=r"(a) : "l"(p));
    return a;
}

__device__ __forceinline__ void cp_async16(uint32_t saddr, const void* g, unsigned src_bytes) {
    asm volatile("cp.async.cg.shared.global [%0], [%1], 16, %2;\n"
                 :: "r"(saddr), "l"(g), "r"(src_bytes));
}

__device__ __forceinline__ void ldsm_x4(uint32_t& r0, uint32_t& r1, uint32_t& r2, uint32_t& r3,
                                        uint32_t addr) {
    asm volatile("ldmatrix.sync.aligned.m8n8.x4.shared.b16 {%0,%1,%2,%3}, [%4];"
                 : "=r"(r0), "=r"(r1), "=r"(r2), "=r"(r3) : "r"(addr));
}

__device__ __forceinline__ void mma_f16(float* c, const uint32_t* a, const uint32_t* b) {
    asm volatile("mma.sync.aligned.m16n8k16.row.col.f32.f16.f16.f32 "
                 "{%0,%1,%2,%3}, {%4,%5,%6,%7}, {%8,%9}, {%0,%1,%2,%3};"
                 : "+f"(c[0]), "+f"(c[1]), "+f"(c[2]), "+f"(c[3])
                 : "r"(a[0]), "r"(a[1]), "r"(a[2]), "r"(a[3]), "r"(b[0]), "r"(b[1]));
}

__device__ __forceinline__ float gelu_exact(float v) {
    return 0.5f * v * (1.0f + erff(v * 0.70710678118654752f));
}

// ---------------------------------------------------------------------------
// Kernel 0: zero counters
// ---------------------------------------------------------------------------
__global__ void zero_kernel() {
    int i = threadIdx.x;
    if (i < NEXP) { g_cnt[i] = 0; g_fill[i] = 0; }
}

// ---------------------------------------------------------------------------
// Kernel W: f32 -> fp16 weight conversion (elementwise)
// ---------------------------------------------------------------------------
__global__ void cvt_kernel(const float* __restrict__ src, __half* __restrict__ dst) {
    const int i = blockIdx.x * blockDim.x + threadIdx.x;   // one float4 per thread
    const float4 v = reinterpret_cast<const float4*>(src)[i];
    __half2 h0 = __floats2half2_rn(v.x, v.y);
    __half2 h1 = __floats2half2_rn(v.z, v.w);
    reinterpret_cast<__half2*>(dst)[2 * i]     = h0;
    reinterpret_cast<__half2*>(dst)[2 * i + 1] = h1;
}

// ---------------------------------------------------------------------------
// Kernel 1: fused LayerNorm + router (softmax + top-2) per token.
// ---------------------------------------------------------------------------
__global__ void ln_router_kernel(const float* __restrict__ x,
                                 const float* __restrict__ gamma,
                                 const float* __restrict__ beta,
                                 const float* __restrict__ Wg,
                                 const float* __restrict__ bg) {
    __shared__ float xsh[DMODEL];
    __shared__ float s_sum[8], s_sq[8];
    __shared__ float s_stats[2];
    __shared__ float s_log[NEXP];

    const int t    = blockIdx.x;
    const int tid  = threadIdx.x;
    const int lane = tid & 31;
    const int wid  = tid >> 5;

    const float4 v = reinterpret_cast<const float4*>(x + (size_t)t * DMODEL)[tid];
    float ssum = v.x + v.y + v.z + v.w;
    float ssq  = v.x * v.x + v.y * v.y + v.z * v.z + v.w * v.w;
    #pragma unroll
    for (int o = 16; o; o >>= 1) {
        ssum += __shfl_xor_sync(0xFFFFFFFFu, ssum, o);
        ssq  += __shfl_xor_sync(0xFFFFFFFFu, ssq, o);
    }
    if (lane == 0) { s_sum[wid] = ssum; s_sq[wid] = ssq; }
    __syncthreads();
    if (tid == 0) {
        float a = 0.f, b = 0.f;
        #pragma unroll
        for (int i = 0; i < 8; i++) { a += s_sum[i]; b += s_sq[i]; }
        float mu  = a / (float)DMODEL;
        float var = b / (float)DMODEL - mu * mu;
        s_stats[0] = mu;
        s_stats[1] = rsqrtf(var + EPS_LN);
    }
    __syncthreads();
    const float mu = s_stats[0], rstd = s_stats[1];

    const float4 g  = reinterpret_cast<const float4*>(gamma)[tid];
    const float4 bb = reinterpret_cast<const float4*>(beta)[tid];
    float4 o;
    o.x = (v.x - mu) * rstd * g.x + bb.x;
    o.y = (v.y - mu) * rstd * g.y + bb.y;
    o.z = (v.z - mu) * rstd * g.z + bb.z;
    o.w = (v.w - mu) * rstd * g.w + bb.w;
    reinterpret_cast<float4*>(xsh)[tid] = o;   // full precision for router
    __half2 h0 = __floats2half2_rn(o.x, o.y);
    __half2 h1 = __floats2half2_rn(o.z, o.w);
    __half2* xr = reinterpret_cast<__half2*>(g_xnh + (size_t)t * DMODEL);
    xr[2 * tid]     = h0;
    xr[2 * tid + 1] = h1;
    __syncthreads();

    // warp e computes logit e
    {
        const float* wrow = Wg + wid * DMODEL;
        float acc = 0.f;
        for (int i = lane; i < DMODEL; i += 32) acc += xsh[i] * wrow[i];
        #pragma unroll
        for (int oo = 16; oo; oo >>= 1) acc += __shfl_xor_sync(0xFFFFFFFFu, acc, oo);
        if (lane == 0) s_log[wid] = acc + bg[wid];
    }
    __syncthreads();

    if (tid == 0) {
        float m = -1e30f;
        #pragma unroll
        for (int i = 0; i < NEXP; i++) m = fmaxf(m, s_log[i]);
        float p[NEXP]; float Z = 0.f;
        #pragma unroll
        for (int i = 0; i < NEXP; i++) { p[i] = expf(s_log[i] - m); Z += p[i]; }
        #pragma unroll
        for (int i = 0; i < NEXP; i++) p[i] /= Z;
        int i0 = 0; float p0 = p[0];
        #pragma unroll
        for (int i = 1; i < NEXP; i++) if (p[i] > p0) { p0 = p[i]; i0 = i; }
        int i1 = -1; float p1 = -1e30f;
        #pragma unroll
        for (int i = 0; i < NEXP; i++) if (i != i0 && p[i] > p1) { p1 = p[i]; i1 = i; }
        float denom = p0 + p1 + EPS_TK;
        g_te[2 * t]     = i0;  g_tw[2 * t]     = p0 / denom;
        g_te[2 * t + 1] = i1;  g_tw[2 * t + 1] = p1 / denom;
        atomicAdd(&g_cnt[i0], 1);
        atomicAdd(&g_cnt[i1], 1);
    }
}

// ---------------------------------------------------------------------------
// Kernel 2/3: offsets + scatter
// ---------------------------------------------------------------------------
__global__ void offsets_kernel() {
    if (threadIdx.x == 0) {
        int o = 0;
        #pragma unroll
        for (int e = 0; e < NEXP; e++) { g_off[e] = o; o += g_cnt[e]; }
        g_off[NEXP] = o;
    }
}

__global__ void scatter_kernel() {
    int t = blockIdx.x * blockDim.x + threadIdx.x;
    if (t >= NTOK) return;
    #pragma unroll
    for (int k = 0; k < TOPK; k++) {
        int e   = g_te[2 * t + k];
        int pos = atomicAdd(&g_fill[e], 1);
        int r   = g_off[e] + pos;
        g_tok[r] = t;
        g_wt[r]  = g_tw[2 * t + k];
        g_slot[2 * t + k] = r;
    }
}

// ---------------------------------------------------------------------------
// Kernels 4/5: fp16 mma.sync grouped GEMM (ldmatrix + cp.async, 3 stages,
// 2 CTAs/SM for latency hiding).
//   GELU=true  : h = gelu(Xn[gather] @ W1[e]^T + b1[e])   (N=DFF, K=DMODEL)
//   GELU=false : y = (H @ W2[e]^T + b2[e]) * w            (N=DMODEL, K=DFF)
// CTA 128x128, BK=64 halves (128B rows, XOR swizzle). 8 warps of 64x32.
// ---------------------------------------------------------------------------
#define BM 128
#define BN 128
#define BK 64
#define ATILE (BM * BK * 2)               // 16384 B
#define BTILE (BN * BK * 2)               // 16384 B
#define STAGE (ATILE + BTILE)             // 32768 B
#define NSTAGE 3
#define GEMM_SMEM (NSTAGE * STAGE)        // 98304 B -> 2 CTAs/SM

template <int NTOT, int KDIM, bool GELU>
__global__ __launch_bounds__(256, 2)
void moe_hgemm(const __half* __restrict__ Wh, const float* __restrict__ bias) {
    constexpr int KT = KDIM / BK;

    const int e   = blockIdx.z;
    const int cnt = g_cnt[e];
    const int m0  = blockIdx.y * BM;
    if (m0 >= cnt) return;
    const int off = g_off[e];
    const int n0  = blockIdx.x * BN;

    extern __shared__ char smem[];
    const uint32_t sb = smem_u32(smem);
    const int tid  = threadIdx.x;
    const int lane = tid & 31;
    const int wid  = tid >> 5;
    const int wm   = (wid & 1) * 64;      // warp grid 2(M) x 4(N)
    const int wn   = (wid >> 1) * 32;
    const int grp  = lane >> 2;
    const int tig  = lane & 3;

    // --- loader state (register-slim): row steps by 32 per chunk, so the
    // XOR-swizzle term (q ^ (row&7)) is chunk-invariant; B collapses to
    // base + stride, A keeps per-chunk gather pointers. ---
    const __half* Asrc = GELU ? g_xnh : g_hh;
    const int row0 = tid >> 3;            // 0..31
    const int q    = tid & 7;
    const uint32_t soff0 = (uint32_t)(row0 * 128 + ((q ^ (row0 & 7)) * 16));
    const __half* bptr0 =
        Wh + ((size_t)e * NTOT + n0 + row0) * (size_t)KDIM + q * 8;
    const size_t bstep = (size_t)32 * KDIM;

    const __half* aptr[4]; unsigned abyt[4];
    #pragma unroll
    for (int i = 0; i < 4; i++) {
        int gm = m0 + row0 + i * 32;
        bool v = gm < cnt;
        long ar = GELU ? (v ? (long)g_tok[off + gm] : 0L)
                       : (v ? (long)(off + gm)      : 0L);
        aptr[i] = Asrc + (size_t)ar * KDIM + q * 8;
        abyt[i] = v ? 16u : 0u;
    }

    auto load_stage = [&](int kt) {
        const uint32_t base = sb + (kt % NSTAGE) * STAGE;
        #pragma unroll
        for (int i = 0; i < 4; i++)
            cp_async16(base + soff0 + i * 4096, aptr[i] + kt * BK, abyt[i]);
        #pragma unroll
        for (int i = 0; i < 4; i++)
            cp_async16(base + ATILE + soff0 + i * 4096, bptr0 + i * bstep + kt * BK, 16u);
        asm volatile("cp.async.commit_group;\n" ::);
    };

    // per-lane ldmatrix row constants
    const int lrow = (lane & 7) + ((lane >> 3) & 1) * 8;   // row within 16-row frag
    const int hi   = lane >> 4;                             // k-granule subtile (0/1)

    float acc[4][4][4];
    #pragma unroll
    for (int a = 0; a < 4; a++)
        #pragma unroll
        for (int b = 0; b < 4; b++)
            #pragma unroll
            for (int c = 0; c < 4; c++) acc[a][b][c] = 0.f;

    load_stage(0); load_stage(1);

    for (int kt = 0; kt < KT; ++kt) {
        if (kt + 1 < KT) asm volatile("cp.async.wait_group 1;\n" ::);
        else             asm volatile("cp.async.wait_group 0;\n" ::);
        __syncthreads();

        if (kt + 2 < KT) load_stage(kt + 2);

        const uint32_t base = sb + (kt % NSTAGE) * STAGE;
        #pragma unroll
        for (int ks = 0; ks < 4; ks++) {
            const int gk = ks * 2 + hi;   // k-granule index for this lane's subtile
            uint32_t a[4][4], bf[4][2];
            #pragma unroll
            for (int mf = 0; mf < 4; mf++) {
                int r = wm + mf * 16 + lrow;
                uint32_t addr = base + r * 128 + ((gk ^ (r & 7)) * 16);
                ldsm_x4(a[mf][0], a[mf][1], a[mf][2], a[mf][3], addr);
            }
            #pragma unroll
            for (int nf2 = 0; nf2 < 2; nf2++) {
                int r = wn + nf2 * 16 + lrow;
                uint32_t addr = base + ATILE + r * 128 + ((gk ^ (r & 7)) * 16);
                uint32_t r0, r1, r2, r3;
                ldsm_x4(r0, r1, r2, r3, addr);
                bf[nf2 * 2 + 0][0] = r0; bf[nf2 * 2 + 0][1] = r2;
                bf[nf2 * 2 + 1][0] = r1; bf[nf2 * 2 + 1][1] = r3;
            }
            #pragma unroll
            for (int mf = 0; mf < 4; mf++)
                #pragma unroll
                for (int nf = 0; nf < 4; nf++)
                    mma_f16(acc[mf][nf], a[mf], bf[nf]);
        }
    }

    // --- epilogue ---
    const float* brow = bias + (size_t)e * NTOT;
    #pragma unroll
    for (int mf = 0; mf < 4; mf++) {
        #pragma unroll
        for (int half = 0; half < 2; half++) {
            const int rl = wm + mf * 16 + grp + half * 8;
            const int gm = m0 + rl;
            if (gm >= cnt) continue;
            const int grow = off + gm;
            if (GELU) {
                __half* orow = g_hh + (size_t)grow * NTOT;
                #pragma unroll
                for (int nf = 0; nf < 4; nf++) {
                    const int col = n0 + wn + nf * 8 + tig * 2;
                    float c0 = acc[mf][nf][half * 2 + 0] + brow[col];
                    float c1 = acc[mf][nf][half * 2 + 1] + brow[col + 1];
                    *reinterpret_cast<__half2*>(orow + col) =
                        __floats2half2_rn(gelu_exact(c0), gelu_exact(c1));
                }
            } else {
                const float scale = g_wt[grow];
                float* orow = g_y + (size_t)grow * NTOT;
                #pragma unroll
                for (int nf = 0; nf < 4; nf++) {
                    const int col = n0 + wn + nf * 8 + tig * 2;
                    float2 st;
                    st.x = (acc[mf][nf][half * 2 + 0] + brow[col])     * scale;
                    st.y = (acc[mf][nf][half * 2 + 1] + brow[col + 1]) * scale;
                    *reinterpret_cast<float2*>(orow + col) = st;
                }
            }
        }
    }
}

// ---------------------------------------------------------------------------
// Kernel 6: residual combine  out[t] = x[t] + y[slot0] + y[slot1]
// ---------------------------------------------------------------------------
__global__ void combine_kernel(const float* __restrict__ x, float* __restrict__ out) {
    const int t   = blockIdx.x;
    const int tid = threadIdx.x;
    const int s0  = g_slot[2 * t];
    const int s1  = g_slot[2 * t + 1];
    const float4 xv = reinterpret_cast<const float4*>(x + (size_t)t * DMODEL)[tid];
    const float4 y0 = reinterpret_cast<const float4*>(g_y + (size_t)s0 * DMODEL)[tid];
    const float4 y1 = reinterpret_cast<const float4*>(g_y + (size_t)s1 * DMODEL)[tid];
    float4 o;
    o.x = xv.x + y0.x + y1.x;
    o.y = xv.y + y0.y + y1.y;
    o.z = xv.z + y0.z + y1.z;
    o.w = xv.w + y0.w + y1.w;
    reinterpret_cast<float4*>(out + (size_t)t * DMODEL)[tid] = o;
}

// ---------------------------------------------------------------------------
// Entry point
// ---------------------------------------------------------------------------
extern "C" void kernel_launch(void* const* d_in, const int* in_sizes, int n_in,
                              void* d_out, int out_size) {
    (void)in_sizes; (void)n_in; (void)out_size;
    const float* x     = (const float*)d_in[0];
    const float* gamma = (const float*)d_in[1];
    const float* beta  = (const float*)d_in[2];
    const float* Wg    = (const float*)d_in[3];
    const float* bg    = (const float*)d_in[4];
    const float* W1    = (const float*)d_in[5];
    const float* b1    = (const float*)d_in[6];
    const float* W2    = (const float*)d_in[7];
    const float* b2    = (const float*)d_in[8];
    float* out = (float*)d_out;

    cudaFuncSetAttribute(moe_hgemm<DFF, DMODEL, true>,
                         cudaFuncAttributeMaxDynamicSharedMemorySize, GEMM_SMEM);
    cudaFuncSetAttribute(moe_hgemm<DMODEL, DFF, false>,
                         cudaFuncAttributeMaxDynamicSharedMemorySize, GEMM_SMEM);

    __half* w1h; cudaGetSymbolAddress((void**)&w1h, g_w1h);
    __half* w2h; cudaGetSymbolAddress((void**)&w2h, g_w2h);

    const int WELEM = NEXP * DFF * DMODEL;          // 33,554,432
    cvt_kernel<<<WELEM / (256 * 4), 256>>>(W1, w1h);
    cvt_kernel<<<WELEM / (256 * 4), 256>>>(W2, w2h);

    zero_kernel<<<1, 32>>>();
    ln_router_kernel<<<NTOK, 256>>>(x, gamma, beta, Wg, bg);
    offsets_kernel<<<1, 1>>>();
    scatter_kernel<<<(NTOK + 255) / 256, 256>>>();

    // GEMM1: h = gelu(xn @ W1^T + b1)
    moe_hgemm<DFF, DMODEL, true>
        <<<dim3(DFF / BN, NTOK / BM, NEXP), 256, GEMM_SMEM>>>(w1h, b1);
    // GEMM2: y = (h @ W2^T + b2) * w
    moe_hgemm<DMODEL, DFF, false>
        <<<dim3(DMODEL / BN, NTOK / BM, NEXP), 256, GEMM_SMEM>>>(w2h, b2);

    combine_kernel<<<NTOK, 256>>>(x, out);
}

// round 10
// speedup vs baseline: 1.9218x; 1.0430x over previous
#include <cuda_runtime.h>
#include <cuda_fp16.h>
#include <math.h>
#include <stdint.h>

// Problem constants (fixed by the reference)
#define DMODEL 1024
#define NEXP   8
#define TOPK   2
#define NTOK   4096          // B*S = 2*2048
#define DFF    4096
#define EPS_LN 1e-5f
#define EPS_TK 1e-8f

// ---------------------------------------------------------------------------
// Scratch (device globals: no allocations allowed)
// ---------------------------------------------------------------------------
__device__ __half g_xnh[(size_t)NTOK * DMODEL];                // 8 MB   normalized input (fp16)
__device__ __half g_hh [(size_t)NTOK * TOPK * DFF];            // 67 MB  GEMM1 output (post-gelu, fp16)
__device__ float  g_y  [(size_t)NTOK * TOPK * DMODEL];         // 33 MB  GEMM2 output (weighted)
__device__ __half g_w1h[(size_t)NEXP * DFF * DMODEL];          // 67 MB  W1 fp16
__device__ __half g_w2h[(size_t)NEXP * DMODEL * DFF];          // 67 MB  W2 fp16
__device__ int    g_cnt [NEXP];
__device__ int    g_fill[NEXP];
__device__ int    g_off [NEXP + 1];
__device__ int    g_tok [NTOK * TOPK];
__device__ float  g_wt  [NTOK * TOPK];
__device__ int    g_slot[NTOK * TOPK];
__device__ int    g_te  [NTOK * TOPK];
__device__ float  g_tw  [NTOK * TOPK];

// ---------------------------------------------------------------------------
// Helpers
// ---------------------------------------------------------------------------
__device__ __forceinline__ uint32_t smem_u32(const void* p) {
    uint32_t a;
    asm("{ .reg .u64 t; cvta.to.shared.u64 t, %1; cvt.u32.u64 %0, t; }" : "=r"(a) : "l"(p));
    return a;
}

__device__ __forceinline__ void cp_async16(uint32_t saddr, const void* g, unsigned src_bytes) {
    asm volatile("cp.async.cg.shared.global [%0], [%1], 16, %2;\n"
                 :: "r"(saddr), "l"(g), "r"(src_bytes));
}

__device__ __forceinline__ void ldsm_x4(uint32_t& r0, uint32_t& r1, uint32_t& r2, uint32_t& r3,
                                        uint32_t addr) {
    asm volatile("ldmatrix.sync.aligned.m8n8.x4.shared.b16 {%0,%1,%2,%3}, [%4];"
                 : "=r"(r0), "=r"(r1), "=r"(r2), "=r"(r3) : "r"(addr));
}

__device__ __forceinline__ void mma_f16(float* c, const uint32_t* a, const uint32_t* b) {
    asm volatile("mma.sync.aligned.m16n8k16.row.col.f32.f16.f16.f32 "
                 "{%0,%1,%2,%3}, {%4,%5,%6,%7}, {%8,%9}, {%0,%1,%2,%3};"
                 : "+f"(c[0]), "+f"(c[1]), "+f"(c[2]), "+f"(c[3])
                 : "r"(a[0]), "r"(a[1]), "r"(a[2]), "r"(a[3]), "r"(b[0]), "r"(b[1]));
}

__device__ __forceinline__ float gelu_exact(float v) {
    return 0.5f * v * (1.0f + erff(v * 0.70710678118654752f));
}

// ---------------------------------------------------------------------------
// Kernel 0: zero counters
// ---------------------------------------------------------------------------
__global__ void zero_kernel() {
    int i = threadIdx.x;
    if (i < NEXP) { g_cnt[i] = 0; g_fill[i] = 0; }
}

// ---------------------------------------------------------------------------
// Kernel W: f32 -> fp16 weight conversion (elementwise)
// ---------------------------------------------------------------------------
__global__ void cvt_kernel(const float* __restrict__ src, __half* __restrict__ dst) {
    const int i = blockIdx.x * blockDim.x + threadIdx.x;   // one float4 per thread
    const float4 v = reinterpret_cast<const float4*>(src)[i];
    __half2 h0 = __floats2half2_rn(v.x, v.y);
    __half2 h1 = __floats2half2_rn(v.z, v.w);
    reinterpret_cast<__half2*>(dst)[2 * i]     = h0;
    reinterpret_cast<__half2*>(dst)[2 * i + 1] = h1;
}

// ---------------------------------------------------------------------------
// Kernel 1: fused LayerNorm + router (softmax + top-2) per token.
// ---------------------------------------------------------------------------
__global__ void ln_router_kernel(const float* __restrict__ x,
                                 const float* __restrict__ gamma,
                                 const float* __restrict__ beta,
                                 const float* __restrict__ Wg,
                                 const float* __restrict__ bg) {
    __shared__ float xsh[DMODEL];
    __shared__ float s_sum[8], s_sq[8];
    __shared__ float s_stats[2];
    __shared__ float s_log[NEXP];

    const int t    = blockIdx.x;
    const int tid  = threadIdx.x;
    const int lane = tid & 31;
    const int wid  = tid >> 5;

    const float4 v = reinterpret_cast<const float4*>(x + (size_t)t * DMODEL)[tid];
    float ssum = v.x + v.y + v.z + v.w;
    float ssq  = v.x * v.x + v.y * v.y + v.z * v.z + v.w * v.w;
    #pragma unroll
    for (int o = 16; o; o >>= 1) {
        ssum += __shfl_xor_sync(0xFFFFFFFFu, ssum, o);
        ssq  += __shfl_xor_sync(0xFFFFFFFFu, ssq, o);
    }
    if (lane == 0) { s_sum[wid] = ssum; s_sq[wid] = ssq; }
    __syncthreads();
    if (tid == 0) {
        float a = 0.f, b = 0.f;
        #pragma unroll
        for (int i = 0; i < 8; i++) { a += s_sum[i]; b += s_sq[i]; }
        float mu  = a / (float)DMODEL;
        float var = b / (float)DMODEL - mu * mu;
        s_stats[0] = mu;
        s_stats[1] = rsqrtf(var + EPS_LN);
    }
    __syncthreads();
    const float mu = s_stats[0], rstd = s_stats[1];

    const float4 g  = reinterpret_cast<const float4*>(gamma)[tid];
    const float4 bb = reinterpret_cast<const float4*>(beta)[tid];
    float4 o;
    o.x = (v.x - mu) * rstd * g.x + bb.x;
    o.y = (v.y - mu) * rstd * g.y + bb.y;
    o.z = (v.z - mu) * rstd * g.z + bb.z;
    o.w = (v.w - mu) * rstd * g.w + bb.w;
    reinterpret_cast<float4*>(xsh)[tid] = o;   // full precision for router
    __half2 h0 = __floats2half2_rn(o.x, o.y);
    __half2 h1 = __floats2half2_rn(o.z, o.w);
    __half2* xr = reinterpret_cast<__half2*>(g_xnh + (size_t)t * DMODEL);
    xr[2 * tid]     = h0;
    xr[2 * tid + 1] = h1;
    __syncthreads();

    // warp e computes logit e
    {
        const float* wrow = Wg + wid * DMODEL;
        float acc = 0.f;
        for (int i = lane; i < DMODEL; i += 32) acc += xsh[i] * wrow[i];
        #pragma unroll
        for (int oo = 16; oo; oo >>= 1) acc += __shfl_xor_sync(0xFFFFFFFFu, acc, oo);
        if (lane == 0) s_log[wid] = acc + bg[wid];
    }
    __syncthreads();

    if (tid == 0) {
        float m = -1e30f;
        #pragma unroll
        for (int i = 0; i < NEXP; i++) m = fmaxf(m, s_log[i]);
        float p[NEXP]; float Z = 0.f;
        #pragma unroll
        for (int i = 0; i < NEXP; i++) { p[i] = expf(s_log[i] - m); Z += p[i]; }
        #pragma unroll
        for (int i = 0; i < NEXP; i++) p[i] /= Z;
        int i0 = 0; float p0 = p[0];
        #pragma unroll
        for (int i = 1; i < NEXP; i++) if (p[i] > p0) { p0 = p[i]; i0 = i; }
        int i1 = -1; float p1 = -1e30f;
        #pragma unroll
        for (int i = 0; i < NEXP; i++) if (i != i0 && p[i] > p1) { p1 = p[i]; i1 = i; }
        float denom = p0 + p1 + EPS_TK;
        g_te[2 * t]     = i0;  g_tw[2 * t]     = p0 / denom;
        g_te[2 * t + 1] = i1;  g_tw[2 * t + 1] = p1 / denom;
        atomicAdd(&g_cnt[i0], 1);
        atomicAdd(&g_cnt[i1], 1);
    }
}

// ---------------------------------------------------------------------------
// Kernel 2/3: offsets + scatter
// ---------------------------------------------------------------------------
__global__ void offsets_kernel() {
    if (threadIdx.x == 0) {
        int o = 0;
        #pragma unroll
        for (int e = 0; e < NEXP; e++) { g_off[e] = o; o += g_cnt[e]; }
        g_off[NEXP] = o;
    }
}

__global__ void scatter_kernel() {
    int t = blockIdx.x * blockDim.x + threadIdx.x;
    if (t >= NTOK) return;
    #pragma unroll
    for (int k = 0; k < TOPK; k++) {
        int e   = g_te[2 * t + k];
        int pos = atomicAdd(&g_fill[e], 1);
        int r   = g_off[e] + pos;
        g_tok[r] = t;
        g_wt[r]  = g_tw[2 * t + k];
        g_slot[2 * t + k] = r;
    }
}

// ---------------------------------------------------------------------------
// Kernels 4/5: fp16 mma.sync grouped GEMM (ldmatrix + cp.async, 3 stages,
// 2 CTAs/SM for latency hiding).
//   GELU=true  : h = gelu(Xn[gather] @ W1[e]^T + b1[e])   (N=DFF, K=DMODEL)
//   GELU=false : y = (H @ W2[e]^T + b2[e]) * w            (N=DMODEL, K=DFF)
// CTA 128x128, BK=64 halves (128B rows, XOR swizzle). 8 warps of 64x32.
// ---------------------------------------------------------------------------
#define BM 128
#define BN 128
#define BK 64
#define ATILE (BM * BK * 2)               // 16384 B
#define BTILE (BN * BK * 2)               // 16384 B
#define STAGE (ATILE + BTILE)             // 32768 B
#define NSTAGE 3
#define GEMM_SMEM (NSTAGE * STAGE)        // 98304 B -> 2 CTAs/SM

template <int NTOT, int KDIM, bool GELU>
__global__ __launch_bounds__(256, 2)
void moe_hgemm(const __half* __restrict__ Wh, const float* __restrict__ bias) {
    constexpr int KT = KDIM / BK;

    const int e   = blockIdx.z;
    const int cnt = g_cnt[e];
    const int m0  = blockIdx.y * BM;
    if (m0 >= cnt) return;
    const int off = g_off[e];
    const int n0  = blockIdx.x * BN;

    extern __shared__ char smem[];
    const uint32_t sb = smem_u32(smem);
    const int tid  = threadIdx.x;
    const int lane = tid & 31;
    const int wid  = tid >> 5;
    const int wm   = (wid & 1) * 64;      // warp grid 2(M) x 4(N)
    const int wn   = (wid >> 1) * 32;
    const int grp  = lane >> 2;
    const int tig  = lane & 3;

    // --- loader state (register-slim): row steps by 32 per chunk, so the
    // XOR-swizzle term (q ^ (row&7)) is chunk-invariant; B collapses to
    // base + stride, A keeps per-chunk gather pointers. ---
    const __half* Asrc = GELU ? g_xnh : g_hh;
    const int row0 = tid >> 3;            // 0..31
    const int q    = tid & 7;
    const uint32_t soff0 = (uint32_t)(row0 * 128 + ((q ^ (row0 & 7)) * 16));
    const __half* bptr0 =
        Wh + ((size_t)e * NTOT + n0 + row0) * (size_t)KDIM + q * 8;
    const size_t bstep = (size_t)32 * KDIM;

    const __half* aptr[4]; unsigned abyt[4];
    #pragma unroll
    for (int i = 0; i < 4; i++) {
        int gm = m0 + row0 + i * 32;
        bool v = gm < cnt;
        long ar = GELU ? (v ? (long)g_tok[off + gm] : 0L)
                       : (v ? (long)(off + gm)      : 0L);
        aptr[i] = Asrc + (size_t)ar * KDIM + q * 8;
        abyt[i] = v ? 16u : 0u;
    }

    auto load_stage = [&](int kt) {
        const uint32_t base = sb + (kt % NSTAGE) * STAGE;
        #pragma unroll
        for (int i = 0; i < 4; i++)
            cp_async16(base + soff0 + i * 4096, aptr[i] + kt * BK, abyt[i]);
        #pragma unroll
        for (int i = 0; i < 4; i++)
            cp_async16(base + ATILE + soff0 + i * 4096, bptr0 + i * bstep + kt * BK, 16u);
        asm volatile("cp.async.commit_group;\n" ::);
    };

    // per-lane ldmatrix row constants
    const int lrow = (lane & 7) + ((lane >> 3) & 1) * 8;   // row within 16-row frag
    const int hi   = lane >> 4;                             // k-granule subtile (0/1)

    float acc[4][4][4];
    #pragma unroll
    for (int a = 0; a < 4; a++)
        #pragma unroll
        for (int b = 0; b < 4; b++)
            #pragma unroll
            for (int c = 0; c < 4; c++) acc[a][b][c] = 0.f;

    load_stage(0); load_stage(1);

    for (int kt = 0; kt < KT; ++kt) {
        if (kt + 1 < KT) asm volatile("cp.async.wait_group 1;\n" ::);
        else             asm volatile("cp.async.wait_group 0;\n" ::);
        __syncthreads();

        if (kt + 2 < KT) load_stage(kt + 2);

        const uint32_t base = sb + (kt % NSTAGE) * STAGE;
        #pragma unroll
        for (int ks = 0; ks < 4; ks++) {
            const int gk = ks * 2 + hi;   // k-granule index for this lane's subtile
            uint32_t a[4][4], bf[4][2];
            #pragma unroll
            for (int mf = 0; mf < 4; mf++) {
                int r = wm + mf * 16 + lrow;
                uint32_t addr = base + r * 128 + ((gk ^ (r & 7)) * 16);
                ldsm_x4(a[mf][0], a[mf][1], a[mf][2], a[mf][3], addr);
            }
            #pragma unroll
            for (int nf2 = 0; nf2 < 2; nf2++) {
                int r = wn + nf2 * 16 + lrow;
                uint32_t addr = base + ATILE + r * 128 + ((gk ^ (r & 7)) * 16);
                uint32_t r0, r1, r2, r3;
                ldsm_x4(r0, r1, r2, r3, addr);
                bf[nf2 * 2 + 0][0] = r0; bf[nf2 * 2 + 0][1] = r2;
                bf[nf2 * 2 + 1][0] = r1; bf[nf2 * 2 + 1][1] = r3;
            }
            #pragma unroll
            for (int mf = 0; mf < 4; mf++)
                #pragma unroll
                for (int nf = 0; nf < 4; nf++)
                    mma_f16(acc[mf][nf], a[mf], bf[nf]);
        }
    }

    // --- epilogue ---
    const float* brow = bias + (size_t)e * NTOT;
    #pragma unroll
    for (int mf = 0; mf < 4; mf++) {
        #pragma unroll
        for (int half = 0; half < 2; half++) {
            const int rl = wm + mf * 16 + grp + half * 8;
            const int gm = m0 + rl;
            if (gm >= cnt) continue;
            const int grow = off + gm;
            if (GELU) {
                __half* orow = g_hh + (size_t)grow * NTOT;
                #pragma unroll
                for (int nf = 0; nf < 4; nf++) {
                    const int col = n0 + wn + nf * 8 + tig * 2;
                    float c0 = acc[mf][nf][half * 2 + 0] + brow[col];
                    float c1 = acc[mf][nf][half * 2 + 1] + brow[col + 1];
                    *reinterpret_cast<__half2*>(orow + col) =
                        __floats2half2_rn(gelu_exact(c0), gelu_exact(c1));
                }
            } else {
                const float scale = g_wt[grow];
                float* orow = g_y + (size_t)grow * NTOT;
                #pragma unroll
                for (int nf = 0; nf < 4; nf++) {
                    const int col = n0 + wn + nf * 8 + tig * 2;
                    float2 st;
                    st.x = (acc[mf][nf][half * 2 + 0] + brow[col])     * scale;
                    st.y = (acc[mf][nf][half * 2 + 1] + brow[col + 1]) * scale;
                    *reinterpret_cast<float2*>(orow + col) = st;
                }
            }
        }
    }
}

// ---------------------------------------------------------------------------
// Kernel 6: residual combine  out[t] = x[t] + y[slot0] + y[slot1]
// ---------------------------------------------------------------------------
__global__ void combine_kernel(const float* __restrict__ x, float* __restrict__ out) {
    const int t   = blockIdx.x;
    const int tid = threadIdx.x;
    const int s0  = g_slot[2 * t];
    const int s1  = g_slot[2 * t + 1];
    const float4 xv = reinterpret_cast<const float4*>(x + (size_t)t * DMODEL)[tid];
    const float4 y0 = reinterpret_cast<const float4*>(g_y + (size_t)s0 * DMODEL)[tid];
    const float4 y1 = reinterpret_cast<const float4*>(g_y + (size_t)s1 * DMODEL)[tid];
    float4 o;
    o.x = xv.x + y0.x + y1.x;
    o.y = xv.y + y0.y + y1.y;
    o.z = xv.z + y0.z + y1.z;
    o.w = xv.w + y0.w + y1.w;
    reinterpret_cast<float4*>(out + (size_t)t * DMODEL)[tid] = o;
}

// ---------------------------------------------------------------------------
// Entry point.
// Side stream overlaps weight conversion with the LN/router chain (cvt_W1)
// and with GEMM1 (cvt_W2), using the standard capture-fork/join pattern:
// identical device work every call; stream/events created once (host-side
// resources only, no device memory allocation).
// ---------------------------------------------------------------------------
extern "C" void kernel_launch(void* const* d_in, const int* in_sizes, int n_in,
                              void* d_out, int out_size) {
    (void)in_sizes; (void)n_in; (void)out_size;
    const float* x     = (const float*)d_in[0];
    const float* gamma = (const float*)d_in[1];
    const float* beta  = (const float*)d_in[2];
    const float* Wg    = (const float*)d_in[3];
    const float* bg    = (const float*)d_in[4];
    const float* W1    = (const float*)d_in[5];
    const float* b1    = (const float*)d_in[6];
    const float* W2    = (const float*)d_in[7];
    const float* b2    = (const float*)d_in[8];
    float* out = (float*)d_out;

    static cudaStream_t s_cvt = nullptr;
    static cudaEvent_t ev_root = nullptr, ev_w1 = nullptr, ev_w2 = nullptr;
    if (s_cvt == nullptr) {
        cudaStreamCreateWithFlags(&s_cvt, cudaStreamNonBlocking);
        cudaEventCreateWithFlags(&ev_root, cudaEventDisableTiming);
        cudaEventCreateWithFlags(&ev_w1, cudaEventDisableTiming);
        cudaEventCreateWithFlags(&ev_w2, cudaEventDisableTiming);
    }

    cudaFuncSetAttribute(moe_hgemm<DFF, DMODEL, true>,
                         cudaFuncAttributeMaxDynamicSharedMemorySize, GEMM_SMEM);
    cudaFuncSetAttribute(moe_hgemm<DMODEL, DFF, false>,
                         cudaFuncAttributeMaxDynamicSharedMemorySize, GEMM_SMEM);

    __half* w1h; cudaGetSymbolAddress((void**)&w1h, g_w1h);
    __half* w2h; cudaGetSymbolAddress((void**)&w2h, g_w2h);

    const int WELEM = NEXP * DFF * DMODEL;          // 33,554,432

    // Fork: weight conversions on the side stream.
    cudaEventRecord(ev_root, 0);
    cudaStreamWaitEvent(s_cvt, ev_root, 0);
    cvt_kernel<<<WELEM / (256 * 4), 256, 0, s_cvt>>>(W1, w1h);
    cudaEventRecord(ev_w1, s_cvt);
    cvt_kernel<<<WELEM / (256 * 4), 256, 0, s_cvt>>>(W2, w2h);
    cudaEventRecord(ev_w2, s_cvt);

    // Main chain: LN + routing (concurrent with cvt_W1).
    zero_kernel<<<1, 32>>>();
    ln_router_kernel<<<NTOK, 256>>>(x, gamma, beta, Wg, bg);
    offsets_kernel<<<1, 1>>>();
    scatter_kernel<<<(NTOK + 255) / 256, 256>>>();

    // Join W1, run GEMM1 (cvt_W2 hides underneath it).
    cudaStreamWaitEvent(0, ev_w1, 0);
    moe_hgemm<DFF, DMODEL, true>
        <<<dim3(DFF / BN, NTOK / BM, NEXP), 256, GEMM_SMEM>>>(w1h, b1);

    // Join W2, run GEMM2.
    cudaStreamWaitEvent(0, ev_w2, 0);
    moe_hgemm<DMODEL, DFF, false>
        <<<dim3(DMODEL / BN, NTOK / BM, NEXP), 256, GEMM_SMEM>>>(w2h, b2);

    combine_kernel<<<NTOK, 256>>>(x, out);
}